// round 15
// baseline (speedup 1.0000x reference)
#include <cuda_runtime.h>
#include <cuda_bf16.h>
#include <math.h>
#include <stdint.h>

#define N_NODES 100000
#define N_PAD 100096                                // padded for mma tile OOB reads
#define E_EDGES 1600000
#define IN_F 20
#define H_F 64
#define NHEADS 4
#define HO_F 32
#define EPS_BN 1e-5f
#define SCAN_B 512
#define NB_SCAN ((N_NODES + SCAN_B - 1) / SCAN_B)   // 196

// ---------------- scratch (device globals; no allocation) ----------------
__device__ int    d_cnt[N_NODES];                   // self-resetting (zero after scan1)
__device__ int    d_rowptr[N_NODES + 1];
__device__ int    d_cursor[N_NODES];
__device__ int    d_bsum[NB_SCAN];
__device__ int    d_csr_src[E_EDGES];
__device__ __align__(16) float d_aggrx[N_NODES * IN_F];
__device__ __align__(16) unsigned long long d_h1p[N_NODES * 32]; // h1 packed f32 pairs (25.6MB)
__device__ float  d_u[512];                          // folded att vectors
__device__ unsigned int d_wgfrag[8192];              // B fragments (bf16 pairs, 32KB)
__device__ float4 d_asrc4[N_NODES];
__device__ float4 d_adst4[N_NODES];
__device__ __align__(16) unsigned int d_aggat_u[N_PAD * 128]; // [n][h][pairs] bf16
__device__ __align__(16) unsigned long long d_h2p[N_NODES * 32]; // h2 packed f32 pairs

// ---------------- helpers ----------------
__device__ __forceinline__ unsigned int f2bf(float a, float b) {
    __nv_bfloat162 p = __float22bfloat162_rn(make_float2(a, b));
    return *reinterpret_cast<unsigned int*>(&p);
}
__device__ __forceinline__ unsigned long long pk2(float a, float b) {
    unsigned long long r;
    asm("mov.b64 %0, {%1,%2};" : "=l"(r) : "f"(a), "f"(b));
    return r;
}
__device__ __forceinline__ unsigned long long fma2(unsigned long long a,
                                                   unsigned long long b,
                                                   unsigned long long c) {
    unsigned long long d;
    asm("fma.rn.f32x2 %0, %1, %2, %3;" : "=l"(d) : "l"(a), "l"(b), "l"(c));
    return d;
}
__device__ __forceinline__ unsigned long long add2(unsigned long long a,
                                                   unsigned long long b) {
    unsigned long long d;
    asm("add.rn.f32x2 %0, %1, %2;" : "=l"(d) : "l"(a), "l"(b));
    return d;
}
__device__ __forceinline__ float2 upk2(unsigned long long v) {
    float2 f;
    asm("mov.b64 {%0,%1}, %2;" : "=f"(f.x), "=f"(f.y) : "l"(v));
    return f;
}
__device__ __forceinline__ void mma16816(float& c0, float& c1, float& c2, float& c3,
                                         unsigned int a0, unsigned int a1,
                                         unsigned int a2, unsigned int a3,
                                         unsigned int b0, unsigned int b1) {
    asm volatile("mma.sync.aligned.m16n8k16.row.col.f32.bf16.bf16.f32 "
                 "{%0,%1,%2,%3}, {%4,%5,%6,%7}, {%8,%9}, {%0,%1,%2,%3};"
                 : "+f"(c0), "+f"(c1), "+f"(c2), "+f"(c3)
                 : "r"(a0), "r"(a1), "r"(a2), "r"(a3), "r"(b0), "r"(b1));
}

// ---------------- CSR build ----------------
__global__ void k_count(const int* __restrict__ ei) {
    int e = blockIdx.x * blockDim.x + threadIdx.x;
    if (e >= E_EDGES) return;
    atomicAdd(&d_cnt[ei[E_EDGES + e]], 1);
}
__global__ void k_scan1() {
    __shared__ int sd[SCAN_B];
    int tid = threadIdx.x;
    int i = blockIdx.x * SCAN_B + tid;
    int v = (i < N_NODES) ? d_cnt[i] : 0;
    if (i < N_NODES) d_cnt[i] = 0;
    sd[tid] = v;
    __syncthreads();
    for (int o = 1; o < SCAN_B; o <<= 1) {
        int t = (tid >= o) ? sd[tid - o] : 0;
        __syncthreads();
        sd[tid] += t;
        __syncthreads();
    }
    if (i < N_NODES) d_rowptr[i] = sd[tid] - v;
    if (tid == SCAN_B - 1) d_bsum[blockIdx.x] = sd[tid];
}
__global__ void k_scan23() {
    __shared__ int sd[256];
    int tid = threadIdx.x;
    int bv = (tid < NB_SCAN) ? d_bsum[tid] : 0;
    sd[tid] = bv;
    __syncthreads();
    for (int o = 1; o < 256; o <<= 1) {
        int t = (tid >= o) ? sd[tid - o] : 0;
        __syncthreads();
        sd[tid] += t;
        __syncthreads();
    }
    int off = (blockIdx.x == 0) ? 0 : sd[blockIdx.x - 1];
    for (int k = 0; k < SCAN_B; k += 256) {
        int i = blockIdx.x * SCAN_B + k + tid;
        if (i < N_NODES) {
            int r = d_rowptr[i] + off;
            d_rowptr[i] = r;
            d_cursor[i] = r;
        }
    }
    if (blockIdx.x == 0 && tid == 0) d_rowptr[N_NODES] = E_EDGES;
}
__global__ void k_scatter(const int* __restrict__ ei) {
    int e = blockIdx.x * blockDim.x + threadIdx.x;
    if (e >= E_EDGES) return;
    int s = ei[e], d = ei[E_EDGES + e];
    int pos = atomicAdd(&d_cursor[d], 1);
    d_csr_src[pos] = s;
}

// ---------------- prep: folded att vectors + bf16 B fragments for mma ----------
__global__ void k_prep(const float* __restrict__ Wg,
                       const float* __restrict__ att_src,
                       const float* __restrict__ att_dst) {
    int tid = blockIdx.x * blockDim.x + threadIdx.x;
    if (tid < 512) {
        int idx = tid & 255;
        int h = idx >> 6, k = idx & 63;
        const float* att = (tid < 256) ? att_src : att_dst;
        float acc = 0.0f;
#pragma unroll 8
        for (int d = 0; d < 64; d++)
            acc += Wg[k * 256 + h * 64 + d] * att[h * 64 + d];
        d_u[tid] = acc;
    } else if (tid < 512 + 8192) {
        int t2 = tid - 512;
        int reg = t2 & 1;
        int lane = (t2 >> 1) & 31;
        int ks = (t2 >> 6) & 15;
        int nt = t2 >> 10;
        int n = nt * 8 + (lane >> 2);
        int k0 = ks * 16 + 2 * (lane & 3) + reg * 8;
        int k1 = k0 + 1;
        float b0 = 0.25f * Wg[(k0 & 63) * 256 + (k0 >> 6) * 64 + n];
        float b1 = 0.25f * Wg[(k1 & 63) * 256 + (k1 >> 6) * 64 + n];
        d_wgfrag[t2] = f2bf(b0, b1);
    }
}

// ---------------- SAGE1 mean aggregation v3 — lane-per-dim, all edges ----------
__global__ __launch_bounds__(256) void k_sage1_csr(const float* __restrict__ x) {
    int n = blockIdx.x * 8 + (threadIdx.x >> 5);
    int lane = threadIdx.x & 31;
    if (n >= N_NODES) return;
    int row = d_rowptr[n];
    int deg = d_rowptr[n + 1] - row;
    bool fl = lane < IN_F;
    float acc = 0.0f;
#pragma unroll 4
    for (int e = 0; e < deg; e++) {
        int s = __ldg(&d_csr_src[row + e]);           // warp-broadcast LDG
        if (fl) acc += __ldg(&x[(size_t)s * IN_F + lane]);
    }
    if (fl) {
        float inv = 1.0f / fmaxf((float)deg, 1.0f);
        d_aggrx[(size_t)n * IN_F + lane] = acc * inv;
    }
}

// ---------------- SAGE1 GEMM + BN + ReLU + packed-f32 store + att logits -------
__global__ __launch_bounds__(256) void k_sage1_gemm(const float* __restrict__ x,
                             const float* __restrict__ Wl, const float* __restrict__ Wr,
                             const float* __restrict__ b,
                             const float* __restrict__ g, const float* __restrict__ be,
                             const float* __restrict__ m, const float* __restrict__ v) {
    __shared__ float sWl[IN_F * H_F], sWr[IN_F * H_F];
    __shared__ float sred[8][8];
    for (int i = threadIdx.x; i < IN_F * H_F; i += blockDim.x) { sWl[i] = Wl[i]; sWr[i] = Wr[i]; }
    __syncthreads();
    int t = blockIdx.x * blockDim.x + threadIdx.x;
    int n = t >> 6, j = t & 63;
    const float* ax = d_aggrx + (size_t)n * IN_F;
    const float* xr = x + (size_t)n * IN_F;
    float acc = b[j];
#pragma unroll
    for (int k = 0; k < IN_F; k++) {
        acc = fmaf(ax[k], sWl[k * H_F + j], acc);
        acc = fmaf(xr[k], sWr[k * H_F + j], acc);
    }
    float sc = g[j] * rsqrtf(v[j] + EPS_BN);
    float y = fmaxf((acc - m[j]) * sc + be[j], 0.0f);
    float ynext = __shfl_down_sync(0xffffffffu, y, 1);
    if ((j & 1) == 0) d_h1p[t >> 1] = pk2(y, ynext);
    float pv[8];
#pragma unroll
    for (int h = 0; h < 4; h++) {
        pv[h]     = y * __ldg(&d_u[h * 64 + j]);
        pv[4 + h] = y * __ldg(&d_u[256 + h * 64 + j]);
    }
#pragma unroll
    for (int o = 16; o; o >>= 1) {
#pragma unroll
        for (int q = 0; q < 8; q++) pv[q] += __shfl_xor_sync(0xffffffffu, pv[q], o);
    }
    int w = threadIdx.x >> 5;
    if ((threadIdx.x & 31) == 0) {
#pragma unroll
        for (int q = 0; q < 8; q++) sred[w][q] = pv[q];
    }
    __syncthreads();
    if (threadIdx.x < 32) {
        int node = threadIdx.x >> 3, q = threadIdx.x & 7;
        float val = sred[node * 2][q] + sred[node * 2 + 1][q];
        int nn = blockIdx.x * 4 + node;
        if (q < 4) ((float*)d_asrc4)[nn * 4 + q] = val;
        else       ((float*)d_adst4)[nn * 4 + q - 4] = val;
    }
}

// ---------------- GAT fused single-pass v3 — packed-f32 loads, packed-exp smem -
__global__ __launch_bounds__(256) void k_gat_csr() {
    __shared__ unsigned long long sExpP[8][4][32];
    int w = threadIdx.x >> 5, lane = threadIdx.x & 31;
    int n = blockIdx.x * 8 + w;
    if (n >= N_NODES) return;
    int row = d_rowptr[n];
    int deg = d_rowptr[n + 1] - row;
    float4 ad = d_adst4[n];
    unsigned long long acc0 = 0ull, acc1 = 0ull, acc2 = 0ull, acc3 = 0ull;
    float4 den = make_float4(0.f, 0.f, 0.f, 0.f);
    for (int c = 0; c < deg; c += 32) {
        int idx = c + lane;
        bool val = idx < deg;
        int s_l = val ? __ldg(&d_csr_src[row + idx]) : 0;
        float4 a = d_asrc4[s_l];
        float t; float4 ex;
        t = a.x + ad.x; t = t > 0.f ? t : 0.2f * t; ex.x = __expf(t);
        t = a.y + ad.y; t = t > 0.f ? t : 0.2f * t; ex.y = __expf(t);
        t = a.z + ad.z; t = t > 0.f ? t : 0.2f * t; ex.z = __expf(t);
        t = a.w + ad.w; t = t > 0.f ? t : 0.2f * t; ex.w = __expf(t);
        if (!val) { ex.x = 0.f; ex.y = 0.f; ex.z = 0.f; ex.w = 0.f; }
        den.x += ex.x; den.y += ex.y; den.z += ex.z; den.w += ex.w;
        sExpP[w][0][lane] = pk2(ex.x, ex.x);
        sExpP[w][1][lane] = pk2(ex.y, ex.y);
        sExpP[w][2][lane] = pk2(ex.z, ex.z);
        sExpP[w][3][lane] = pk2(ex.w, ex.w);
        __syncwarp();
        int kmax = min(32, deg - c);
#pragma unroll 4
        for (int i = 0; i < kmax; i++) {
            int s = __ldg(&d_csr_src[row + c + i]);                  // warp-broadcast
            unsigned long long f = __ldg(&d_h1p[(size_t)s * 32 + lane]); // packed f32x2
            acc0 = fma2(sExpP[w][0][i], f, acc0);
            acc1 = fma2(sExpP[w][1][i], f, acc1);
            acc2 = fma2(sExpP[w][2][i], f, acc2);
            acc3 = fma2(sExpP[w][3][i], f, acc3);
        }
        __syncwarp();
    }
#pragma unroll
    for (int o = 16; o; o >>= 1) {
        den.x += __shfl_xor_sync(0xffffffffu, den.x, o);
        den.y += __shfl_xor_sync(0xffffffffu, den.y, o);
        den.z += __shfl_xor_sync(0xffffffffu, den.z, o);
        den.w += __shfl_xor_sync(0xffffffffu, den.w, o);
    }
    float id0 = 1.0f / (den.x + 1e-16f);
    float id1 = 1.0f / (den.y + 1e-16f);
    float id2 = 1.0f / (den.z + 1e-16f);
    float id3 = 1.0f / (den.w + 1e-16f);
    unsigned int* out = d_aggat_u + (size_t)n * 128;
    float2 f;
    f = upk2(acc0); out[0 * 32 + lane] = f2bf(f.x * id0, f.y * id0);
    f = upk2(acc1); out[1 * 32 + lane] = f2bf(f.x * id1, f.y * id1);
    f = upk2(acc2); out[2 * 32 + lane] = f2bf(f.x * id2, f.y * id2);
    f = upk2(acc3); out[3 * 32 + lane] = f2bf(f.x * id3, f.y * id3);
}

// ---------------- GAT post GEMM on HMMA tensor cores ---------------------------
__global__ __launch_bounds__(256) void k_gat_post(const float* __restrict__ bg,
                                                  const float* __restrict__ g2,
                                                  const float* __restrict__ be2,
                                                  const float* __restrict__ m2,
                                                  const float* __restrict__ v2) {
    int w = threadIdx.x >> 5, lane = threadIdx.x & 31;
    int nbase = blockIdx.x * 128 + w * 16;
    int row0 = nbase + (lane >> 2);
    int row1 = row0 + 8;
    const unsigned int* A0 = d_aggat_u + (size_t)row0 * 128;
    const unsigned int* A1 = d_aggat_u + (size_t)row1 * 128;
    float c[8][4];
#pragma unroll
    for (int nt = 0; nt < 8; nt++)
#pragma unroll
        for (int q = 0; q < 4; q++) c[nt][q] = 0.0f;
#pragma unroll 4
    for (int ks = 0; ks < 16; ks++) {
        int p = ks * 8 + (lane & 3);
        unsigned int a0 = __ldg(&A0[p]);
        unsigned int a1 = __ldg(&A1[p]);
        unsigned int a2 = __ldg(&A0[p + 4]);
        unsigned int a3 = __ldg(&A1[p + 4]);
#pragma unroll
        for (int nt = 0; nt < 8; nt++) {
            int bidx = ((nt * 16 + ks) * 32 + lane) * 2;
            unsigned int b0 = __ldg(&d_wgfrag[bidx]);
            unsigned int b1 = __ldg(&d_wgfrag[bidx + 1]);
            mma16816(c[nt][0], c[nt][1], c[nt][2], c[nt][3], a0, a1, a2, a3, b0, b1);
        }
    }
    bool v0 = row0 < N_NODES, v1 = row1 < N_NODES;
#pragma unroll
    for (int nt = 0; nt < 8; nt++) {
        int j = nt * 8 + 2 * (lane & 3);
        float sc0 = __ldg(&g2[j])     * rsqrtf(__ldg(&v2[j])     + EPS_BN);
        float sc1 = __ldg(&g2[j + 1]) * rsqrtf(__ldg(&v2[j + 1]) + EPS_BN);
        float cb0 = __ldg(&bg[j])     - __ldg(&m2[j]);
        float cb1 = __ldg(&bg[j + 1]) - __ldg(&m2[j + 1]);
        float eb0 = __ldg(&be2[j]), eb1 = __ldg(&be2[j + 1]);
        if (v0) {
            float y0 = fmaxf((c[nt][0] + cb0) * sc0 + eb0, 0.0f);
            float y1 = fmaxf((c[nt][1] + cb1) * sc1 + eb1, 0.0f);
            d_h2p[(size_t)row0 * 32 + (j >> 1)] = pk2(y0, y1);
        }
        if (v1) {
            float y2 = fmaxf((c[nt][2] + cb0) * sc0 + eb0, 0.0f);
            float y3 = fmaxf((c[nt][3] + cb1) * sc1 + eb1, 0.0f);
            d_h2p[(size_t)row1 * 32 + (j >> 1)] = pk2(y2, y3);
        }
    }
}

// ---------------- SAGE3: fused aggregation + GEMM + BN + skip + classifier -----
__global__ __launch_bounds__(256) void k_sage3_cls(const float* __restrict__ x,
                             const float* __restrict__ Wl, const float* __restrict__ Wr,
                             const float* __restrict__ b,
                             const float* __restrict__ g, const float* __restrict__ be,
                             const float* __restrict__ m, const float* __restrict__ v,
                             const float* __restrict__ Wskip, const float* __restrict__ bskip,
                             const float* __restrict__ Wc1, const float* __restrict__ bc1,
                             const float* __restrict__ Wc2, const float* __restrict__ bc2,
                             float* __restrict__ out) {
    __shared__ float sWl[H_F * HO_F], sWr[H_F * HO_F], sWs[IN_F * HO_F];
    __shared__ float sW1[32 * 32], sb1[32], sW2[64];
    __shared__ float2 sAgg[8][32];
    for (int i = threadIdx.x; i < H_F * HO_F; i += blockDim.x) { sWl[i] = Wl[i]; sWr[i] = Wr[i]; }
    for (int i = threadIdx.x; i < IN_F * HO_F; i += blockDim.x) sWs[i] = Wskip[i];
    for (int i = threadIdx.x; i < 32 * 32; i += blockDim.x) sW1[i] = Wc1[i];
    if (threadIdx.x < 32) sb1[threadIdx.x] = bc1[threadIdx.x];
    else if (threadIdx.x < 96) sW2[threadIdx.x - 32] = Wc2[threadIdx.x - 32];
    __syncthreads();
    int w = threadIdx.x >> 5;
    int lane = threadIdx.x & 31;
    int n = blockIdx.x * 8 + w;
    if (n >= N_NODES) return;
    int row = d_rowptr[n];
    int deg = d_rowptr[n + 1] - row;
    unsigned long long accp = 0ull;
#pragma unroll 4
    for (int e = 0; e < deg; e++) {
        int s = __ldg(&d_csr_src[row + e]);                 // warp-broadcast
        accp = add2(accp, __ldg(&d_h2p[(size_t)s * 32 + lane]));
    }
    {
        float2 fa = upk2(accp);
        float inv = 1.0f / fmaxf((float)deg, 1.0f);
        sAgg[w][lane] = make_float2(fa.x * inv, fa.y * inv);
    }
    __syncwarp();
    int j = lane;
    const unsigned long long* h2row = d_h2p + (size_t)n * 32;
    float acc = b[j];
#pragma unroll
    for (int kp = 0; kp < 32; kp++) {
        float2 av = sAgg[w][kp];
        float2 hv = upk2(__ldg(&h2row[kp]));
        acc = fmaf(av.x, sWl[(2 * kp) * HO_F + j], acc);
        acc = fmaf(av.y, sWl[(2 * kp + 1) * HO_F + j], acc);
        acc = fmaf(hv.x, sWr[(2 * kp) * HO_F + j], acc);
        acc = fmaf(hv.y, sWr[(2 * kp + 1) * HO_F + j], acc);
    }
    float ident = bskip[j];
    const float* xr = x + (size_t)n * IN_F;
#pragma unroll
    for (int k = 0; k < IN_F; k++) ident = fmaf(xr[k], sWs[k * HO_F + j], ident);
    float sc = g[j] * rsqrtf(v[j] + EPS_BN);
    float y = (acc - m[j]) * sc + be[j];
    float hv = fmaxf(y, 0.0f) + ident;
    float s = sb1[j];
#pragma unroll
    for (int k = 0; k < 32; k++) {
        float bb = __shfl_sync(0xffffffffu, hv, k);
        s = fmaf(bb, sW1[k * 32 + j], s);
    }
    s = fmaxf(s, 0.0f);
    float p0 = s * sW2[j * 2];
    float p1 = s * sW2[j * 2 + 1];
#pragma unroll
    for (int o = 16; o; o >>= 1) {
        p0 += __shfl_down_sync(0xffffffffu, p0, o);
        p1 += __shfl_down_sync(0xffffffffu, p1, o);
    }
    if (j == 0) {
        float l0 = p0 + bc2[0], l1 = p1 + bc2[1];
        float mx = fmaxf(l0, l1);
        float lse = mx + logf(__expf(l0 - mx) + __expf(l1 - mx));
        out[(size_t)n * 2]     = l0 - lse;
        out[(size_t)n * 2 + 1] = l1 - lse;
    }
}

// ---------------- launch ----------------
extern "C" void kernel_launch(void* const* d_in, const int* in_sizes, int n_in,
                              void* d_out, int out_size) {
    const float* x       = (const float*)d_in[0];
    const int*   ei      = (const int*)d_in[1];
    const float* W1l     = (const float*)d_in[2];
    const float* W1r     = (const float*)d_in[3];
    const float* b1      = (const float*)d_in[4];
    const float* g1      = (const float*)d_in[5];
    const float* be1     = (const float*)d_in[6];
    const float* m1      = (const float*)d_in[7];
    const float* v1      = (const float*)d_in[8];
    const float* Wg      = (const float*)d_in[9];
    const float* att_src = (const float*)d_in[10];
    const float* att_dst = (const float*)d_in[11];
    const float* bg      = (const float*)d_in[12];
    const float* g2      = (const float*)d_in[13];
    const float* be2     = (const float*)d_in[14];
    const float* m2      = (const float*)d_in[15];
    const float* v2      = (const float*)d_in[16];
    const float* W3l     = (const float*)d_in[17];
    const float* W3r     = (const float*)d_in[18];
    const float* b3      = (const float*)d_in[19];
    const float* g3      = (const float*)d_in[20];
    const float* be3     = (const float*)d_in[21];
    const float* m3      = (const float*)d_in[22];
    const float* v3      = (const float*)d_in[23];
    const float* Wskip   = (const float*)d_in[24];
    const float* bskip   = (const float*)d_in[25];
    const float* Wc1     = (const float*)d_in[26];
    const float* bc1     = (const float*)d_in[27];
    const float* Wc2     = (const float*)d_in[28];
    const float* bc2     = (const float*)d_in[29];
    float* out = (float*)d_out;

    const int TPB = 256;
    k_count<<<(E_EDGES + TPB - 1) / TPB, TPB>>>(ei);
    k_scan1<<<NB_SCAN, SCAN_B>>>();
    k_scan23<<<NB_SCAN, 256>>>();
    k_scatter<<<(E_EDGES + TPB - 1) / TPB, TPB>>>(ei);
    k_sage1_csr<<<(N_NODES + 7) / 8, TPB>>>(x);
    k_prep<<<34, 256>>>(Wg, att_src, att_dst);
    k_sage1_gemm<<<(N_NODES * H_F) / TPB, TPB>>>(x, W1l, W1r, b1, g1, be1, m1, v1);
    k_gat_csr<<<(N_NODES + 7) / 8, TPB>>>();
    k_gat_post<<<(N_NODES + 127) / 128, 256>>>(bg, g2, be2, m2, v2);
    k_sage3_cls<<<(N_NODES + 7) / 8, TPB>>>(x, W3l, W3r, b3, g3, be3, m3, v3, Wskip, bskip,
                                            Wc1, bc1, Wc2, bc2, out);
}

// round 16
// speedup vs baseline: 1.0827x; 1.0827x over previous
#include <cuda_runtime.h>
#include <cuda_bf16.h>
#include <math.h>
#include <stdint.h>

#define N_NODES 100000
#define N_PAD 100096                                // padded for mma tile OOB reads
#define E_EDGES 1600000
#define IN_F 20
#define H_F 64
#define NHEADS 4
#define HO_F 32
#define EPS_BN 1e-5f
#define SCAN_B 512
#define NB_SCAN ((N_NODES + SCAN_B - 1) / SCAN_B)   // 196

// ---------------- scratch (device globals; no allocation) ----------------
__device__ int    d_cnt[N_NODES];                   // self-resetting (zero after scan1)
__device__ int    d_rowptr[N_NODES + 1];
__device__ int    d_cursor[N_NODES];
__device__ int    d_bsum[NB_SCAN];
__device__ int    d_csr_src[E_EDGES];
__device__ __align__(16) float d_aggrx[N_NODES * IN_F];
__device__ __align__(16) unsigned int d_h1bu[N_NODES * 32];   // h1 bf16 pairs (12.8MB)
__device__ float  d_u[512];                          // folded att vectors
__device__ unsigned int d_wgfrag[8192];              // B fragments (bf16 pairs, 32KB)
__device__ float4 d_asrc4[N_NODES];
__device__ float4 d_adst4[N_NODES];
__device__ __align__(16) unsigned int d_aggat_u[N_PAD * 128]; // [n][h][pairs] bf16
__device__ __align__(16) unsigned int d_h2bu[N_NODES * 32];   // h2 bf16 pairs

// ---------------- helpers ----------------
__device__ __forceinline__ float2 bf2f(unsigned int u) {
    __nv_bfloat162 b = *reinterpret_cast<__nv_bfloat162*>(&u);
    return __bfloat1622float2(b);
}
__device__ __forceinline__ unsigned int f2bf(float a, float b) {
    __nv_bfloat162 p = __float22bfloat162_rn(make_float2(a, b));
    return *reinterpret_cast<unsigned int*>(&p);
}
__device__ __forceinline__ unsigned long long pk2(float a, float b) {
    unsigned long long r;
    asm("mov.b64 %0, {%1,%2};" : "=l"(r) : "f"(a), "f"(b));
    return r;
}
__device__ __forceinline__ unsigned long long fma2(unsigned long long a,
                                                   unsigned long long b,
                                                   unsigned long long c) {
    unsigned long long d;
    asm("fma.rn.f32x2 %0, %1, %2, %3;" : "=l"(d) : "l"(a), "l"(b), "l"(c));
    return d;
}
__device__ __forceinline__ unsigned long long add2(unsigned long long a,
                                                   unsigned long long b) {
    unsigned long long d;
    asm("add.rn.f32x2 %0, %1, %2;" : "=l"(d) : "l"(a), "l"(b));
    return d;
}
__device__ __forceinline__ float2 upk2(unsigned long long v) {
    float2 f;
    asm("mov.b64 {%0,%1}, %2;" : "=f"(f.x), "=f"(f.y) : "l"(v));
    return f;
}
__device__ __forceinline__ unsigned long long bfp(unsigned int u) {
    unsigned long long d;
    asm("{ .reg .b32 lo, hi;\n\t"
        "shl.b32 lo, %1, 16;\n\t"
        "and.b32 hi, %1, 0xffff0000;\n\t"
        "mov.b64 %0, {lo, hi}; }"
        : "=l"(d) : "r"(u));
    return d;
}
__device__ __forceinline__ void mma16816(float& c0, float& c1, float& c2, float& c3,
                                         unsigned int a0, unsigned int a1,
                                         unsigned int a2, unsigned int a3,
                                         unsigned int b0, unsigned int b1) {
    asm volatile("mma.sync.aligned.m16n8k16.row.col.f32.bf16.bf16.f32 "
                 "{%0,%1,%2,%3}, {%4,%5,%6,%7}, {%8,%9}, {%0,%1,%2,%3};"
                 : "+f"(c0), "+f"(c1), "+f"(c2), "+f"(c3)
                 : "r"(a0), "r"(a1), "r"(a2), "r"(a3), "r"(b0), "r"(b1));
}

// ---------------- CSR build ----------------
__global__ void k_count(const int* __restrict__ ei) {
    int e = blockIdx.x * blockDim.x + threadIdx.x;
    if (e >= E_EDGES) return;
    atomicAdd(&d_cnt[ei[E_EDGES + e]], 1);
}
__global__ void k_scan1() {
    __shared__ int sd[SCAN_B];
    int tid = threadIdx.x;
    int i = blockIdx.x * SCAN_B + tid;
    int v = (i < N_NODES) ? d_cnt[i] : 0;
    if (i < N_NODES) d_cnt[i] = 0;
    sd[tid] = v;
    __syncthreads();
    for (int o = 1; o < SCAN_B; o <<= 1) {
        int t = (tid >= o) ? sd[tid - o] : 0;
        __syncthreads();
        sd[tid] += t;
        __syncthreads();
    }
    if (i < N_NODES) d_rowptr[i] = sd[tid] - v;
    if (tid == SCAN_B - 1) d_bsum[blockIdx.x] = sd[tid];
}
__global__ void k_scan23() {
    __shared__ int sd[256];
    int tid = threadIdx.x;
    int bv = (tid < NB_SCAN) ? d_bsum[tid] : 0;
    sd[tid] = bv;
    __syncthreads();
    for (int o = 1; o < 256; o <<= 1) {
        int t = (tid >= o) ? sd[tid - o] : 0;
        __syncthreads();
        sd[tid] += t;
        __syncthreads();
    }
    int off = (blockIdx.x == 0) ? 0 : sd[blockIdx.x - 1];
    for (int k = 0; k < SCAN_B; k += 256) {
        int i = blockIdx.x * SCAN_B + k + tid;
        if (i < N_NODES) {
            int r = d_rowptr[i] + off;
            d_rowptr[i] = r;
            d_cursor[i] = r;
        }
    }
    if (blockIdx.x == 0 && tid == 0) d_rowptr[N_NODES] = E_EDGES;
}
__global__ void k_scatter(const int* __restrict__ ei) {
    int e = blockIdx.x * blockDim.x + threadIdx.x;
    if (e >= E_EDGES) return;
    int s = ei[e], d = ei[E_EDGES + e];
    int pos = atomicAdd(&d_cursor[d], 1);
    d_csr_src[pos] = s;
}

// ---------------- prep: folded att vectors + bf16 B fragments for mma ----------
__global__ void k_prep(const float* __restrict__ Wg,
                       const float* __restrict__ att_src,
                       const float* __restrict__ att_dst) {
    int tid = blockIdx.x * blockDim.x + threadIdx.x;
    if (tid < 512) {
        int idx = tid & 255;
        int h = idx >> 6, k = idx & 63;
        const float* att = (tid < 256) ? att_src : att_dst;
        float acc = 0.0f;
#pragma unroll 8
        for (int d = 0; d < 64; d++)
            acc += Wg[k * 256 + h * 64 + d] * att[h * 64 + d];
        d_u[tid] = acc;
    } else if (tid < 512 + 8192) {
        int t2 = tid - 512;
        int reg = t2 & 1;
        int lane = (t2 >> 1) & 31;
        int ks = (t2 >> 6) & 15;
        int nt = t2 >> 10;
        int n = nt * 8 + (lane >> 2);
        int k0 = ks * 16 + 2 * (lane & 3) + reg * 8;
        int k1 = k0 + 1;
        float b0 = 0.25f * Wg[(k0 & 63) * 256 + (k0 >> 6) * 64 + n];
        float b1 = 0.25f * Wg[(k1 & 63) * 256 + (k1 >> 6) * 64 + n];
        d_wgfrag[t2] = f2bf(b0, b1);
    }
}

// ---------------- SAGE1 mean aggregation v4 — smem-staged idx ------------------
__global__ __launch_bounds__(256) void k_sage1_csr(const float* __restrict__ x) {
    __shared__ int sIdx[8][32];
    int w = threadIdx.x >> 5;
    int n = blockIdx.x * 8 + w;
    int lane = threadIdx.x & 31;
    if (n >= N_NODES) return;
    int row = d_rowptr[n];
    int deg = d_rowptr[n + 1] - row;
    bool fl = lane < IN_F;
    float acc = 0.0f;
    for (int c = 0; c < deg; c += 32) {
        int idx = c + lane;
        if (idx < deg) sIdx[w][lane] = __ldg(&d_csr_src[row + idx]);   // coalesced
        __syncwarp();
        int kmax = min(32, deg - c);
#pragma unroll 4
        for (int i = 0; i < kmax; i++) {
            int s = sIdx[w][i];                                        // LDS broadcast
            if (fl) acc += __ldg(&x[(size_t)s * IN_F + lane]);
        }
        __syncwarp();
    }
    if (fl) {
        float inv = 1.0f / fmaxf((float)deg, 1.0f);
        d_aggrx[(size_t)n * IN_F + lane] = acc * inv;
    }
}

// ---------------- SAGE1 GEMM + BN + ReLU + bf16 pack + fused att logits --------
__global__ __launch_bounds__(256) void k_sage1_gemm(const float* __restrict__ x,
                             const float* __restrict__ Wl, const float* __restrict__ Wr,
                             const float* __restrict__ b,
                             const float* __restrict__ g, const float* __restrict__ be,
                             const float* __restrict__ m, const float* __restrict__ v) {
    __shared__ float sWl[IN_F * H_F], sWr[IN_F * H_F];
    __shared__ float sred[8][8];
    for (int i = threadIdx.x; i < IN_F * H_F; i += blockDim.x) { sWl[i] = Wl[i]; sWr[i] = Wr[i]; }
    __syncthreads();
    int t = blockIdx.x * blockDim.x + threadIdx.x;
    int n = t >> 6, j = t & 63;
    const float* ax = d_aggrx + (size_t)n * IN_F;
    const float* xr = x + (size_t)n * IN_F;
    float acc = b[j];
#pragma unroll
    for (int k = 0; k < IN_F; k++) {
        acc = fmaf(ax[k], sWl[k * H_F + j], acc);
        acc = fmaf(xr[k], sWr[k * H_F + j], acc);
    }
    float sc = g[j] * rsqrtf(v[j] + EPS_BN);
    float y = fmaxf((acc - m[j]) * sc + be[j], 0.0f);
    float ynext = __shfl_down_sync(0xffffffffu, y, 1);
    if ((j & 1) == 0) d_h1bu[t >> 1] = f2bf(y, ynext);
    float pv[8];
#pragma unroll
    for (int h = 0; h < 4; h++) {
        pv[h]     = y * __ldg(&d_u[h * 64 + j]);
        pv[4 + h] = y * __ldg(&d_u[256 + h * 64 + j]);
    }
#pragma unroll
    for (int o = 16; o; o >>= 1) {
#pragma unroll
        for (int q = 0; q < 8; q++) pv[q] += __shfl_xor_sync(0xffffffffu, pv[q], o);
    }
    int w = threadIdx.x >> 5;
    if ((threadIdx.x & 31) == 0) {
#pragma unroll
        for (int q = 0; q < 8; q++) sred[w][q] = pv[q];
    }
    __syncthreads();
    if (threadIdx.x < 32) {
        int node = threadIdx.x >> 3, q = threadIdx.x & 7;
        float val = sred[node * 2][q] + sred[node * 2 + 1][q];
        int nn = blockIdx.x * 4 + node;
        if (q < 4) ((float*)d_asrc4)[nn * 4 + q] = val;
        else       ((float*)d_adst4)[nn * 4 + q - 4] = val;
    }
}

// ---------------- GAT fused single-pass v4 — smem idx + exp, bf16 rows ---------
__global__ __launch_bounds__(256) void k_gat_csr() {
    __shared__ float4 sExp[8][32];
    __shared__ int sIdx[8][32];
    int w = threadIdx.x >> 5, lane = threadIdx.x & 31;
    int n = blockIdx.x * 8 + w;
    if (n >= N_NODES) return;
    int row = d_rowptr[n];
    int deg = d_rowptr[n + 1] - row;
    float4 ad = d_adst4[n];
    unsigned long long acc0 = 0ull, acc1 = 0ull, acc2 = 0ull, acc3 = 0ull;
    float4 den = make_float4(0.f, 0.f, 0.f, 0.f);
    for (int c = 0; c < deg; c += 32) {
        int idx = c + lane;
        bool val = idx < deg;
        int s_l = val ? __ldg(&d_csr_src[row + idx]) : 0;
        float4 a = d_asrc4[s_l];
        float t; float4 ex;
        t = a.x + ad.x; t = t > 0.f ? t : 0.2f * t; ex.x = __expf(t);
        t = a.y + ad.y; t = t > 0.f ? t : 0.2f * t; ex.y = __expf(t);
        t = a.z + ad.z; t = t > 0.f ? t : 0.2f * t; ex.z = __expf(t);
        t = a.w + ad.w; t = t > 0.f ? t : 0.2f * t; ex.w = __expf(t);
        if (!val) { ex.x = 0.f; ex.y = 0.f; ex.z = 0.f; ex.w = 0.f; }
        den.x += ex.x; den.y += ex.y; den.z += ex.z; den.w += ex.w;
        sExp[w][lane] = ex;
        sIdx[w][lane] = s_l;                          // reuse the already-loaded idx
        __syncwarp();
        int kmax = min(32, deg - c);
#pragma unroll 4
        for (int i = 0; i < kmax; i++) {
            int s = sIdx[w][i];                       // LDS broadcast (no LDG)
            float4 e4 = sExp[w][i];                   // LDS broadcast
            unsigned int vv = __ldg(&d_h1bu[(size_t)s * 32 + lane]); // coalesced 128B
            unsigned long long f = bfp(vv);
            acc0 = fma2(pk2(e4.x, e4.x), f, acc0);
            acc1 = fma2(pk2(e4.y, e4.y), f, acc1);
            acc2 = fma2(pk2(e4.z, e4.z), f, acc2);
            acc3 = fma2(pk2(e4.w, e4.w), f, acc3);
        }
        __syncwarp();
    }
#pragma unroll
    for (int o = 16; o; o >>= 1) {
        den.x += __shfl_xor_sync(0xffffffffu, den.x, o);
        den.y += __shfl_xor_sync(0xffffffffu, den.y, o);
        den.z += __shfl_xor_sync(0xffffffffu, den.z, o);
        den.w += __shfl_xor_sync(0xffffffffu, den.w, o);
    }
    float id0 = 1.0f / (den.x + 1e-16f);
    float id1 = 1.0f / (den.y + 1e-16f);
    float id2 = 1.0f / (den.z + 1e-16f);
    float id3 = 1.0f / (den.w + 1e-16f);
    unsigned int* out = d_aggat_u + (size_t)n * 128;
    float2 f;
    f = upk2(acc0); out[0 * 32 + lane] = f2bf(f.x * id0, f.y * id0);
    f = upk2(acc1); out[1 * 32 + lane] = f2bf(f.x * id1, f.y * id1);
    f = upk2(acc2); out[2 * 32 + lane] = f2bf(f.x * id2, f.y * id2);
    f = upk2(acc3); out[3 * 32 + lane] = f2bf(f.x * id3, f.y * id3);
}

// ---------------- GAT post GEMM on HMMA tensor cores ---------------------------
__global__ __launch_bounds__(256) void k_gat_post(const float* __restrict__ bg,
                                                  const float* __restrict__ g2,
                                                  const float* __restrict__ be2,
                                                  const float* __restrict__ m2,
                                                  const float* __restrict__ v2) {
    int w = threadIdx.x >> 5, lane = threadIdx.x & 31;
    int nbase = blockIdx.x * 128 + w * 16;
    int row0 = nbase + (lane >> 2);
    int row1 = row0 + 8;
    const unsigned int* A0 = d_aggat_u + (size_t)row0 * 128;
    const unsigned int* A1 = d_aggat_u + (size_t)row1 * 128;
    float c[8][4];
#pragma unroll
    for (int nt = 0; nt < 8; nt++)
#pragma unroll
        for (int q = 0; q < 4; q++) c[nt][q] = 0.0f;
#pragma unroll 4
    for (int ks = 0; ks < 16; ks++) {
        int p = ks * 8 + (lane & 3);
        unsigned int a0 = __ldg(&A0[p]);
        unsigned int a1 = __ldg(&A1[p]);
        unsigned int a2 = __ldg(&A0[p + 4]);
        unsigned int a3 = __ldg(&A1[p + 4]);
#pragma unroll
        for (int nt = 0; nt < 8; nt++) {
            int bidx = ((nt * 16 + ks) * 32 + lane) * 2;
            unsigned int b0 = __ldg(&d_wgfrag[bidx]);
            unsigned int b1 = __ldg(&d_wgfrag[bidx + 1]);
            mma16816(c[nt][0], c[nt][1], c[nt][2], c[nt][3], a0, a1, a2, a3, b0, b1);
        }
    }
    bool v0 = row0 < N_NODES, v1 = row1 < N_NODES;
#pragma unroll
    for (int nt = 0; nt < 8; nt++) {
        int j = nt * 8 + 2 * (lane & 3);
        float sc0 = __ldg(&g2[j])     * rsqrtf(__ldg(&v2[j])     + EPS_BN);
        float sc1 = __ldg(&g2[j + 1]) * rsqrtf(__ldg(&v2[j + 1]) + EPS_BN);
        float cb0 = __ldg(&bg[j])     - __ldg(&m2[j]);
        float cb1 = __ldg(&bg[j + 1]) - __ldg(&m2[j + 1]);
        float eb0 = __ldg(&be2[j]), eb1 = __ldg(&be2[j + 1]);
        if (v0) {
            float y0 = fmaxf((c[nt][0] + cb0) * sc0 + eb0, 0.0f);
            float y1 = fmaxf((c[nt][1] + cb1) * sc1 + eb1, 0.0f);
            d_h2bu[(size_t)row0 * 32 + (j >> 1)] = f2bf(y0, y1);
        }
        if (v1) {
            float y2 = fmaxf((c[nt][2] + cb0) * sc0 + eb0, 0.0f);
            float y3 = fmaxf((c[nt][3] + cb1) * sc1 + eb1, 0.0f);
            d_h2bu[(size_t)row1 * 32 + (j >> 1)] = f2bf(y2, y3);
        }
    }
}

// ---------------- SAGE3: fused aggregation + GEMM + BN + skip + classifier -----
__global__ __launch_bounds__(256) void k_sage3_cls(const float* __restrict__ x,
                             const float* __restrict__ Wl, const float* __restrict__ Wr,
                             const float* __restrict__ b,
                             const float* __restrict__ g, const float* __restrict__ be,
                             const float* __restrict__ m, const float* __restrict__ v,
                             const float* __restrict__ Wskip, const float* __restrict__ bskip,
                             const float* __restrict__ Wc1, const float* __restrict__ bc1,
                             const float* __restrict__ Wc2, const float* __restrict__ bc2,
                             float* __restrict__ out) {
    __shared__ float sWl[H_F * HO_F], sWr[H_F * HO_F], sWs[IN_F * HO_F];
    __shared__ float sW1[32 * 32], sb1[32], sW2[64];
    __shared__ float2 sAgg[8][32];
    __shared__ int sIdx[8][32];
    for (int i = threadIdx.x; i < H_F * HO_F; i += blockDim.x) { sWl[i] = Wl[i]; sWr[i] = Wr[i]; }
    for (int i = threadIdx.x; i < IN_F * HO_F; i += blockDim.x) sWs[i] = Wskip[i];
    for (int i = threadIdx.x; i < 32 * 32; i += blockDim.x) sW1[i] = Wc1[i];
    if (threadIdx.x < 32) sb1[threadIdx.x] = bc1[threadIdx.x];
    else if (threadIdx.x < 96) sW2[threadIdx.x - 32] = Wc2[threadIdx.x - 32];
    __syncthreads();
    int w = threadIdx.x >> 5;
    int lane = threadIdx.x & 31;
    int n = blockIdx.x * 8 + w;
    if (n >= N_NODES) return;
    int row = d_rowptr[n];
    int deg = d_rowptr[n + 1] - row;
    unsigned long long accp = 0ull;
    for (int c = 0; c < deg; c += 32) {
        int idx = c + lane;
        if (idx < deg) sIdx[w][lane] = __ldg(&d_csr_src[row + idx]);   // coalesced
        __syncwarp();
        int kmax = min(32, deg - c);
#pragma unroll 4
        for (int i = 0; i < kmax; i++) {
            int s = sIdx[w][i];                                        // LDS broadcast
            accp = add2(accp, bfp(__ldg(&d_h2bu[(size_t)s * 32 + lane])));
        }
        __syncwarp();
    }
    {
        float2 fa = upk2(accp);
        float inv = 1.0f / fmaxf((float)deg, 1.0f);
        sAgg[w][lane] = make_float2(fa.x * inv, fa.y * inv);
    }
    __syncwarp();
    int j = lane;
    const unsigned int* h2row = d_h2bu + (size_t)n * 32;
    float acc = b[j];
#pragma unroll
    for (int kp = 0; kp < 32; kp++) {
        float2 av = sAgg[w][kp];
        float2 hv = bf2f(__ldg(&h2row[kp]));
        acc = fmaf(av.x, sWl[(2 * kp) * HO_F + j], acc);
        acc = fmaf(av.y, sWl[(2 * kp + 1) * HO_F + j], acc);
        acc = fmaf(hv.x, sWr[(2 * kp) * HO_F + j], acc);
        acc = fmaf(hv.y, sWr[(2 * kp + 1) * HO_F + j], acc);
    }
    float ident = bskip[j];
    const float* xr = x + (size_t)n * IN_F;
#pragma unroll
    for (int k = 0; k < IN_F; k++) ident = fmaf(xr[k], sWs[k * HO_F + j], ident);
    float sc = g[j] * rsqrtf(v[j] + EPS_BN);
    float y = (acc - m[j]) * sc + be[j];
    float hv = fmaxf(y, 0.0f) + ident;
    float s = sb1[j];
#pragma unroll
    for (int k = 0; k < 32; k++) {
        float bb = __shfl_sync(0xffffffffu, hv, k);
        s = fmaf(bb, sW1[k * 32 + j], s);
    }
    s = fmaxf(s, 0.0f);
    float p0 = s * sW2[j * 2];
    float p1 = s * sW2[j * 2 + 1];
#pragma unroll
    for (int o = 16; o; o >>= 1) {
        p0 += __shfl_down_sync(0xffffffffu, p0, o);
        p1 += __shfl_down_sync(0xffffffffu, p1, o);
    }
    if (j == 0) {
        float l0 = p0 + bc2[0], l1 = p1 + bc2[1];
        float mx = fmaxf(l0, l1);
        float lse = mx + logf(__expf(l0 - mx) + __expf(l1 - mx));
        out[(size_t)n * 2]     = l0 - lse;
        out[(size_t)n * 2 + 1] = l1 - lse;
    }
}

// ---------------- launch ----------------
extern "C" void kernel_launch(void* const* d_in, const int* in_sizes, int n_in,
                              void* d_out, int out_size) {
    const float* x       = (const float*)d_in[0];
    const int*   ei      = (const int*)d_in[1];
    const float* W1l     = (const float*)d_in[2];
    const float* W1r     = (const float*)d_in[3];
    const float* b1      = (const float*)d_in[4];
    const float* g1      = (const float*)d_in[5];
    const float* be1     = (const float*)d_in[6];
    const float* m1      = (const float*)d_in[7];
    const float* v1      = (const float*)d_in[8];
    const float* Wg      = (const float*)d_in[9];
    const float* att_src = (const float*)d_in[10];
    const float* att_dst = (const float*)d_in[11];
    const float* bg      = (const float*)d_in[12];
    const float* g2      = (const float*)d_in[13];
    const float* be2     = (const float*)d_in[14];
    const float* m2      = (const float*)d_in[15];
    const float* v2      = (const float*)d_in[16];
    const float* W3l     = (const float*)d_in[17];
    const float* W3r     = (const float*)d_in[18];
    const float* b3      = (const float*)d_in[19];
    const float* g3      = (const float*)d_in[20];
    const float* be3     = (const float*)d_in[21];
    const float* m3      = (const float*)d_in[22];
    const float* v3      = (const float*)d_in[23];
    const float* Wskip   = (const float*)d_in[24];
    const float* bskip   = (const float*)d_in[25];
    const float* Wc1     = (const float*)d_in[26];
    const float* bc1     = (const float*)d_in[27];
    const float* Wc2     = (const float*)d_in[28];
    const float* bc2     = (const float*)d_in[29];
    float* out = (float*)d_out;

    const int TPB = 256;
    k_count<<<(E_EDGES + TPB - 1) / TPB, TPB>>>(ei);
    k_scan1<<<NB_SCAN, SCAN_B>>>();
    k_scan23<<<NB_SCAN, 256>>>();
    k_scatter<<<(E_EDGES + TPB - 1) / TPB, TPB>>>(ei);
    k_sage1_csr<<<(N_NODES + 7) / 8, TPB>>>(x);
    k_prep<<<34, 256>>>(Wg, att_src, att_dst);
    k_sage1_gemm<<<(N_NODES * H_F) / TPB, TPB>>>(x, W1l, W1r, b1, g1, be1, m1, v1);
    k_gat_csr<<<(N_NODES + 7) / 8, TPB>>>();
    k_gat_post<<<(N_NODES + 127) / 128, 256>>>(bg, g2, be2, m2, v2);
    k_sage3_cls<<<(N_NODES + 7) / 8, TPB>>>(x, W3l, W3r, b3, g3, be3, m3, v3, Wskip, bskip,
                                            Wc1, bc1, Wc2, bc2, out);
}

// round 17
// speedup vs baseline: 1.2799x; 1.1822x over previous
#include <cuda_runtime.h>
#include <cuda_bf16.h>
#include <math.h>
#include <stdint.h>

#define N_NODES 100000
#define N_PAD 100096                                // padded for mma tile OOB reads
#define E_EDGES 1600000
#define IN_F 20
#define H_F 64
#define NHEADS 4
#define HO_F 32
#define EPS_BN 1e-5f
#define SCAN_B 512
#define NB_SCAN ((N_NODES + SCAN_B - 1) / SCAN_B)   // 196

// ---------------- scratch (device globals; no allocation) ----------------
__device__ int    d_cnt[N_NODES];                   // self-resetting (zero after scan1)
__device__ int    d_rowptr[N_NODES + 1];
__device__ int    d_cursor[N_NODES];
__device__ int    d_bsum[NB_SCAN];
__device__ int    d_csr_src[E_EDGES];
__device__ __align__(16) unsigned int d_h1bu[N_NODES * 32];   // h1 bf16 pairs (12.8MB)
__device__ float  d_u[512];                          // folded att vectors
__device__ unsigned int d_wgfrag[8192];              // B fragments (bf16 pairs, 32KB)
__device__ float4 d_asrc4[N_NODES];
__device__ float4 d_adst4[N_NODES];
__device__ __align__(16) unsigned int d_aggat_u[N_PAD * 128]; // [n][h][pairs] bf16
__device__ __align__(16) unsigned int d_h2bu[N_NODES * 32];   // h2 bf16 pairs

// ---------------- helpers ----------------
__device__ __forceinline__ float2 bf2f(unsigned int u) {
    __nv_bfloat162 b = *reinterpret_cast<__nv_bfloat162*>(&u);
    return __bfloat1622float2(b);
}
__device__ __forceinline__ unsigned int f2bf(float a, float b) {
    __nv_bfloat162 p = __float22bfloat162_rn(make_float2(a, b));
    return *reinterpret_cast<unsigned int*>(&p);
}
__device__ __forceinline__ unsigned long long pk2(float a, float b) {
    unsigned long long r;
    asm("mov.b64 %0, {%1,%2};" : "=l"(r) : "f"(a), "f"(b));
    return r;
}
__device__ __forceinline__ unsigned long long fma2(unsigned long long a,
                                                   unsigned long long b,
                                                   unsigned long long c) {
    unsigned long long d;
    asm("fma.rn.f32x2 %0, %1, %2, %3;" : "=l"(d) : "l"(a), "l"(b), "l"(c));
    return d;
}
__device__ __forceinline__ unsigned long long add2(unsigned long long a,
                                                   unsigned long long b) {
    unsigned long long d;
    asm("add.rn.f32x2 %0, %1, %2;" : "=l"(d) : "l"(a), "l"(b));
    return d;
}
__device__ __forceinline__ float2 upk2(unsigned long long v) {
    float2 f;
    asm("mov.b64 {%0,%1}, %2;" : "=f"(f.x), "=f"(f.y) : "l"(v));
    return f;
}
__device__ __forceinline__ unsigned long long bfp(unsigned int u) {
    unsigned long long d;
    asm("{ .reg .b32 lo, hi;\n\t"
        "shl.b32 lo, %1, 16;\n\t"
        "and.b32 hi, %1, 0xffff0000;\n\t"
        "mov.b64 %0, {lo, hi}; }"
        : "=l"(d) : "r"(u));
    return d;
}
__device__ __forceinline__ void mma16816(float& c0, float& c1, float& c2, float& c3,
                                         unsigned int a0, unsigned int a1,
                                         unsigned int a2, unsigned int a3,
                                         unsigned int b0, unsigned int b1) {
    asm volatile("mma.sync.aligned.m16n8k16.row.col.f32.bf16.bf16.f32 "
                 "{%0,%1,%2,%3}, {%4,%5,%6,%7}, {%8,%9}, {%0,%1,%2,%3};"
                 : "+f"(c0), "+f"(c1), "+f"(c2), "+f"(c3)
                 : "r"(a0), "r"(a1), "r"(a2), "r"(a3), "r"(b0), "r"(b1));
}

// ---------------- CSR build ----------------
__global__ void k_count(const int* __restrict__ ei) {
    int e = blockIdx.x * blockDim.x + threadIdx.x;
    if (e >= E_EDGES) return;
    atomicAdd(&d_cnt[ei[E_EDGES + e]], 1);
}
__global__ void k_scan1() {
    __shared__ int sd[SCAN_B];
    int tid = threadIdx.x;
    int i = blockIdx.x * SCAN_B + tid;
    int v = (i < N_NODES) ? d_cnt[i] : 0;
    if (i < N_NODES) d_cnt[i] = 0;
    sd[tid] = v;
    __syncthreads();
    for (int o = 1; o < SCAN_B; o <<= 1) {
        int t = (tid >= o) ? sd[tid - o] : 0;
        __syncthreads();
        sd[tid] += t;
        __syncthreads();
    }
    if (i < N_NODES) d_rowptr[i] = sd[tid] - v;
    if (tid == SCAN_B - 1) d_bsum[blockIdx.x] = sd[tid];
}
__global__ void k_scan23() {
    __shared__ int sd[256];
    int tid = threadIdx.x;
    int bv = (tid < NB_SCAN) ? d_bsum[tid] : 0;
    sd[tid] = bv;
    __syncthreads();
    for (int o = 1; o < 256; o <<= 1) {
        int t = (tid >= o) ? sd[tid - o] : 0;
        __syncthreads();
        sd[tid] += t;
        __syncthreads();
    }
    int off = (blockIdx.x == 0) ? 0 : sd[blockIdx.x - 1];
    for (int k = 0; k < SCAN_B; k += 256) {
        int i = blockIdx.x * SCAN_B + k + tid;
        if (i < N_NODES) {
            int r = d_rowptr[i] + off;
            d_rowptr[i] = r;
            d_cursor[i] = r;
        }
    }
    if (blockIdx.x == 0 && tid == 0) d_rowptr[N_NODES] = E_EDGES;
}
__global__ void k_scatter(const int* __restrict__ ei) {
    int e = blockIdx.x * blockDim.x + threadIdx.x;
    if (e >= E_EDGES) return;
    int s = ei[e], d = ei[E_EDGES + e];
    int pos = atomicAdd(&d_cursor[d], 1);
    d_csr_src[pos] = s;
}

// ---------------- prep: folded att vectors + bf16 B fragments for mma ----------
__global__ void k_prep(const float* __restrict__ Wg,
                       const float* __restrict__ att_src,
                       const float* __restrict__ att_dst) {
    int tid = blockIdx.x * blockDim.x + threadIdx.x;
    if (tid < 512) {
        int idx = tid & 255;
        int h = idx >> 6, k = idx & 63;
        const float* att = (tid < 256) ? att_src : att_dst;
        float acc = 0.0f;
#pragma unroll 8
        for (int d = 0; d < 64; d++)
            acc += Wg[k * 256 + h * 64 + d] * att[h * 64 + d];
        d_u[tid] = acc;
    } else if (tid < 512 + 8192) {
        int t2 = tid - 512;
        int reg = t2 & 1;
        int lane = (t2 >> 1) & 31;
        int ks = (t2 >> 6) & 15;
        int nt = t2 >> 10;
        int n = nt * 8 + (lane >> 2);
        int k0 = ks * 16 + 2 * (lane & 3) + reg * 8;
        int k1 = k0 + 1;
        float b0 = 0.25f * Wg[(k0 & 63) * 256 + (k0 >> 6) * 64 + n];
        float b1 = 0.25f * Wg[(k1 & 63) * 256 + (k1 >> 6) * 64 + n];
        d_wgfrag[t2] = f2bf(b0, b1);
    }
}

// ---------------- SAGE1 fused: gather + GEMM + BN + ReLU + att logits ----------
// warp per node. Phase1: lane-per-dim mean gather of x (smem-staged idx).
// Phase2: lane computes outputs {2*lane, 2*lane+1}; packs own bf16 pair; att
// logits reduced with 40 shfl/node.
__global__ __launch_bounds__(256) void k_sage1_fused(const float* __restrict__ x,
                             const float* __restrict__ Wl, const float* __restrict__ Wr,
                             const float* __restrict__ b,
                             const float* __restrict__ g, const float* __restrict__ be,
                             const float* __restrict__ m, const float* __restrict__ v) {
    __shared__ float sWl[IN_F * H_F], sWr[IN_F * H_F];
    __shared__ float sX[8][IN_F], sA[8][IN_F];
    __shared__ int sIdx[8][32];
    for (int i = threadIdx.x; i < IN_F * H_F; i += blockDim.x) { sWl[i] = Wl[i]; sWr[i] = Wr[i]; }
    __syncthreads();
    int w = threadIdx.x >> 5;
    int lane = threadIdx.x & 31;
    int n = blockIdx.x * 8 + w;
    if (n >= N_NODES) return;
    int row = d_rowptr[n];
    int deg = d_rowptr[n + 1] - row;
    bool fl = lane < IN_F;
    float acc = 0.0f;
    for (int c = 0; c < deg; c += 32) {
        int idx = c + lane;
        if (idx < deg) sIdx[w][lane] = __ldg(&d_csr_src[row + idx]);   // coalesced
        __syncwarp();
        int kmax = min(32, deg - c);
#pragma unroll 4
        for (int i = 0; i < kmax; i++) {
            int s = sIdx[w][i];                                        // LDS broadcast
            if (fl) acc += __ldg(&x[(size_t)s * IN_F + lane]);
        }
        __syncwarp();
    }
    if (fl) {
        float inv = 1.0f / fmaxf((float)deg, 1.0f);
        sA[w][lane] = acc * inv;
        sX[w][lane] = __ldg(&x[(size_t)n * IN_F + lane]);
    }
    __syncwarp();
    // phase 2: outputs j0 = 2*lane, j1 = 2*lane+1
    int j0 = 2 * lane;
    float a0 = __ldg(&b[j0]), a1 = __ldg(&b[j0 + 1]);
#pragma unroll
    for (int k = 0; k < IN_F; k++) {
        float av = sA[w][k], xv = sX[w][k];
        float2 wl = *(const float2*)&sWl[k * H_F + j0];
        float2 wr = *(const float2*)&sWr[k * H_F + j0];
        a0 = fmaf(av, wl.x, a0); a0 = fmaf(xv, wr.x, a0);
        a1 = fmaf(av, wl.y, a1); a1 = fmaf(xv, wr.y, a1);
    }
    float sc0 = __ldg(&g[j0]) * rsqrtf(__ldg(&v[j0]) + EPS_BN);
    float sc1 = __ldg(&g[j0 + 1]) * rsqrtf(__ldg(&v[j0 + 1]) + EPS_BN);
    float y0 = fmaxf((a0 - __ldg(&m[j0])) * sc0 + __ldg(&be[j0]), 0.0f);
    float y1 = fmaxf((a1 - __ldg(&m[j0 + 1])) * sc1 + __ldg(&be[j0 + 1]), 0.0f);
    d_h1bu[(size_t)n * 32 + lane] = f2bf(y0, y1);
    // fused attention logits
    float pv[8];
#pragma unroll
    for (int h = 0; h < 4; h++) {
        pv[h]     = y0 * __ldg(&d_u[h * 64 + j0])       + y1 * __ldg(&d_u[h * 64 + j0 + 1]);
        pv[4 + h] = y0 * __ldg(&d_u[256 + h * 64 + j0]) + y1 * __ldg(&d_u[256 + h * 64 + j0 + 1]);
    }
#pragma unroll
    for (int o = 16; o; o >>= 1) {
#pragma unroll
        for (int q = 0; q < 8; q++) pv[q] += __shfl_xor_sync(0xffffffffu, pv[q], o);
    }
    if (lane == 0) {
        d_asrc4[n] = make_float4(pv[0], pv[1], pv[2], pv[3]);
        d_adst4[n] = make_float4(pv[4], pv[5], pv[6], pv[7]);
    }
}

// ---------------- GAT fused single-pass v4 — smem idx + exp, bf16 rows ---------
__global__ __launch_bounds__(256) void k_gat_csr() {
    __shared__ float4 sExp[8][32];
    __shared__ int sIdx[8][32];
    int w = threadIdx.x >> 5, lane = threadIdx.x & 31;
    int n = blockIdx.x * 8 + w;
    if (n >= N_NODES) return;
    int row = d_rowptr[n];
    int deg = d_rowptr[n + 1] - row;
    float4 ad = d_adst4[n];
    unsigned long long acc0 = 0ull, acc1 = 0ull, acc2 = 0ull, acc3 = 0ull;
    float4 den = make_float4(0.f, 0.f, 0.f, 0.f);
    for (int c = 0; c < deg; c += 32) {
        int idx = c + lane;
        bool val = idx < deg;
        int s_l = val ? __ldg(&d_csr_src[row + idx]) : 0;
        float4 a = d_asrc4[s_l];
        float t; float4 ex;
        t = a.x + ad.x; t = t > 0.f ? t : 0.2f * t; ex.x = __expf(t);
        t = a.y + ad.y; t = t > 0.f ? t : 0.2f * t; ex.y = __expf(t);
        t = a.z + ad.z; t = t > 0.f ? t : 0.2f * t; ex.z = __expf(t);
        t = a.w + ad.w; t = t > 0.f ? t : 0.2f * t; ex.w = __expf(t);
        if (!val) { ex.x = 0.f; ex.y = 0.f; ex.z = 0.f; ex.w = 0.f; }
        den.x += ex.x; den.y += ex.y; den.z += ex.z; den.w += ex.w;
        sExp[w][lane] = ex;
        sIdx[w][lane] = s_l;
        __syncwarp();
        int kmax = min(32, deg - c);
#pragma unroll 4
        for (int i = 0; i < kmax; i++) {
            int s = sIdx[w][i];                       // LDS broadcast (no LDG)
            float4 e4 = sExp[w][i];                   // LDS broadcast
            unsigned int vv = __ldg(&d_h1bu[(size_t)s * 32 + lane]); // coalesced 128B
            unsigned long long f = bfp(vv);
            acc0 = fma2(pk2(e4.x, e4.x), f, acc0);
            acc1 = fma2(pk2(e4.y, e4.y), f, acc1);
            acc2 = fma2(pk2(e4.z, e4.z), f, acc2);
            acc3 = fma2(pk2(e4.w, e4.w), f, acc3);
        }
        __syncwarp();
    }
#pragma unroll
    for (int o = 16; o; o >>= 1) {
        den.x += __shfl_xor_sync(0xffffffffu, den.x, o);
        den.y += __shfl_xor_sync(0xffffffffu, den.y, o);
        den.z += __shfl_xor_sync(0xffffffffu, den.z, o);
        den.w += __shfl_xor_sync(0xffffffffu, den.w, o);
    }
    float id0 = 1.0f / (den.x + 1e-16f);
    float id1 = 1.0f / (den.y + 1e-16f);
    float id2 = 1.0f / (den.z + 1e-16f);
    float id3 = 1.0f / (den.w + 1e-16f);
    unsigned int* out = d_aggat_u + (size_t)n * 128;
    float2 f;
    f = upk2(acc0); out[0 * 32 + lane] = f2bf(f.x * id0, f.y * id0);
    f = upk2(acc1); out[1 * 32 + lane] = f2bf(f.x * id1, f.y * id1);
    f = upk2(acc2); out[2 * 32 + lane] = f2bf(f.x * id2, f.y * id2);
    f = upk2(acc3); out[3 * 32 + lane] = f2bf(f.x * id3, f.y * id3);
}

// ---------------- GAT post GEMM on HMMA tensor cores (smem-staged B) -----------
__global__ __launch_bounds__(256) void k_gat_post(const float* __restrict__ bg,
                                                  const float* __restrict__ g2,
                                                  const float* __restrict__ be2,
                                                  const float* __restrict__ m2,
                                                  const float* __restrict__ v2) {
    __shared__ unsigned int sB[8192];                 // 32 KB B-fragment table
    int tid = threadIdx.x;
    {
        const uint4* src = (const uint4*)d_wgfrag;
        uint4* dst = (uint4*)sB;
#pragma unroll
        for (int r = 0; r < 8; r++) dst[tid + r * 256] = __ldg(&src[tid + r * 256]);
    }
    __syncthreads();
    int w = tid >> 5, lane = tid & 31;
    int nbase = blockIdx.x * 128 + w * 16;
    int row0 = nbase + (lane >> 2);
    int row1 = row0 + 8;
    const unsigned int* A0 = d_aggat_u + (size_t)row0 * 128;
    const unsigned int* A1 = d_aggat_u + (size_t)row1 * 128;
    float c[8][4];
#pragma unroll
    for (int nt = 0; nt < 8; nt++)
#pragma unroll
        for (int q = 0; q < 4; q++) c[nt][q] = 0.0f;
#pragma unroll 4
    for (int ks = 0; ks < 16; ks++) {
        int p = ks * 8 + (lane & 3);
        unsigned int a0 = __ldg(&A0[p]);
        unsigned int a1 = __ldg(&A1[p]);
        unsigned int a2 = __ldg(&A0[p + 4]);
        unsigned int a3 = __ldg(&A1[p + 4]);
#pragma unroll
        for (int nt = 0; nt < 8; nt++) {
            uint2 bb = *(const uint2*)&sB[((nt * 16 + ks) * 32 + lane) * 2];
            mma16816(c[nt][0], c[nt][1], c[nt][2], c[nt][3], a0, a1, a2, a3, bb.x, bb.y);
        }
    }
    bool v0 = row0 < N_NODES, v1 = row1 < N_NODES;
#pragma unroll
    for (int nt = 0; nt < 8; nt++) {
        int j = nt * 8 + 2 * (lane & 3);
        float sc0 = __ldg(&g2[j])     * rsqrtf(__ldg(&v2[j])     + EPS_BN);
        float sc1 = __ldg(&g2[j + 1]) * rsqrtf(__ldg(&v2[j + 1]) + EPS_BN);
        float cb0 = __ldg(&bg[j])     - __ldg(&m2[j]);
        float cb1 = __ldg(&bg[j + 1]) - __ldg(&m2[j + 1]);
        float eb0 = __ldg(&be2[j]), eb1 = __ldg(&be2[j + 1]);
        if (v0) {
            float y0 = fmaxf((c[nt][0] + cb0) * sc0 + eb0, 0.0f);
            float y1 = fmaxf((c[nt][1] + cb1) * sc1 + eb1, 0.0f);
            d_h2bu[(size_t)row0 * 32 + (j >> 1)] = f2bf(y0, y1);
        }
        if (v1) {
            float y2 = fmaxf((c[nt][2] + cb0) * sc0 + eb0, 0.0f);
            float y3 = fmaxf((c[nt][3] + cb1) * sc1 + eb1, 0.0f);
            d_h2bu[(size_t)row1 * 32 + (j >> 1)] = f2bf(y2, y3);
        }
    }
}

// ---------------- SAGE3: fused aggregation + GEMM + BN + skip + classifier -----
__global__ __launch_bounds__(256) void k_sage3_cls(const float* __restrict__ x,
                             const float* __restrict__ Wl, const float* __restrict__ Wr,
                             const float* __restrict__ b,
                             const float* __restrict__ g, const float* __restrict__ be,
                             const float* __restrict__ m, const float* __restrict__ v,
                             const float* __restrict__ Wskip, const float* __restrict__ bskip,
                             const float* __restrict__ Wc1, const float* __restrict__ bc1,
                             const float* __restrict__ Wc2, const float* __restrict__ bc2,
                             float* __restrict__ out) {
    __shared__ float sWl[H_F * HO_F], sWr[H_F * HO_F], sWs[IN_F * HO_F];
    __shared__ float sW1[32 * 32], sb1[32], sW2[64];
    __shared__ float2 sAgg[8][32];
    __shared__ int sIdx[8][32];
    for (int i = threadIdx.x; i < H_F * HO_F; i += blockDim.x) { sWl[i] = Wl[i]; sWr[i] = Wr[i]; }
    for (int i = threadIdx.x; i < IN_F * HO_F; i += blockDim.x) sWs[i] = Wskip[i];
    for (int i = threadIdx.x; i < 32 * 32; i += blockDim.x) sW1[i] = Wc1[i];
    if (threadIdx.x < 32) sb1[threadIdx.x] = bc1[threadIdx.x];
    else if (threadIdx.x < 96) sW2[threadIdx.x - 32] = Wc2[threadIdx.x - 32];
    __syncthreads();
    int w = threadIdx.x >> 5;
    int lane = threadIdx.x & 31;
    int n = blockIdx.x * 8 + w;
    if (n >= N_NODES) return;
    int row = d_rowptr[n];
    int deg = d_rowptr[n + 1] - row;
    unsigned long long accp = 0ull;
    for (int c = 0; c < deg; c += 32) {
        int idx = c + lane;
        if (idx < deg) sIdx[w][lane] = __ldg(&d_csr_src[row + idx]);   // coalesced
        __syncwarp();
        int kmax = min(32, deg - c);
#pragma unroll 4
        for (int i = 0; i < kmax; i++) {
            int s = sIdx[w][i];                                        // LDS broadcast
            accp = add2(accp, bfp(__ldg(&d_h2bu[(size_t)s * 32 + lane])));
        }
        __syncwarp();
    }
    {
        float2 fa = upk2(accp);
        float inv = 1.0f / fmaxf((float)deg, 1.0f);
        sAgg[w][lane] = make_float2(fa.x * inv, fa.y * inv);
    }
    __syncwarp();
    int j = lane;
    const unsigned int* h2row = d_h2bu + (size_t)n * 32;
    float acc = b[j];
#pragma unroll
    for (int kp = 0; kp < 32; kp++) {
        float2 av = sAgg[w][kp];
        float2 hv = bf2f(__ldg(&h2row[kp]));
        acc = fmaf(av.x, sWl[(2 * kp) * HO_F + j], acc);
        acc = fmaf(av.y, sWl[(2 * kp + 1) * HO_F + j], acc);
        acc = fmaf(hv.x, sWr[(2 * kp) * HO_F + j], acc);
        acc = fmaf(hv.y, sWr[(2 * kp + 1) * HO_F + j], acc);
    }
    float ident = bskip[j];
    const float* xr = x + (size_t)n * IN_F;
#pragma unroll
    for (int k = 0; k < IN_F; k++) ident = fmaf(xr[k], sWs[k * HO_F + j], ident);
    float sc = g[j] * rsqrtf(v[j] + EPS_BN);
    float y = (acc - m[j]) * sc + be[j];
    float hv = fmaxf(y, 0.0f) + ident;
    float s = sb1[j];
#pragma unroll
    for (int k = 0; k < 32; k++) {
        float bb = __shfl_sync(0xffffffffu, hv, k);
        s = fmaf(bb, sW1[k * 32 + j], s);
    }
    s = fmaxf(s, 0.0f);
    float p0 = s * sW2[j * 2];
    float p1 = s * sW2[j * 2 + 1];
#pragma unroll
    for (int o = 16; o; o >>= 1) {
        p0 += __shfl_down_sync(0xffffffffu, p0, o);
        p1 += __shfl_down_sync(0xffffffffu, p1, o);
    }
    if (j == 0) {
        float l0 = p0 + bc2[0], l1 = p1 + bc2[1];
        float mx = fmaxf(l0, l1);
        float lse = mx + logf(__expf(l0 - mx) + __expf(l1 - mx));
        out[(size_t)n * 2]     = l0 - lse;
        out[(size_t)n * 2 + 1] = l1 - lse;
    }
}

// ---------------- launch ----------------
extern "C" void kernel_launch(void* const* d_in, const int* in_sizes, int n_in,
                              void* d_out, int out_size) {
    const float* x       = (const float*)d_in[0];
    const int*   ei      = (const int*)d_in[1];
    const float* W1l     = (const float*)d_in[2];
    const float* W1r     = (const float*)d_in[3];
    const float* b1      = (const float*)d_in[4];
    const float* g1      = (const float*)d_in[5];
    const float* be1     = (const float*)d_in[6];
    const float* m1      = (const float*)d_in[7];
    const float* v1      = (const float*)d_in[8];
    const float* Wg      = (const float*)d_in[9];
    const float* att_src = (const float*)d_in[10];
    const float* att_dst = (const float*)d_in[11];
    const float* bg      = (const float*)d_in[12];
    const float* g2      = (const float*)d_in[13];
    const float* be2     = (const float*)d_in[14];
    const float* m2      = (const float*)d_in[15];
    const float* v2      = (const float*)d_in[16];
    const float* W3l     = (const float*)d_in[17];
    const float* W3r     = (const float*)d_in[18];
    const float* b3      = (const float*)d_in[19];
    const float* g3      = (const float*)d_in[20];
    const float* be3     = (const float*)d_in[21];
    const float* m3      = (const float*)d_in[22];
    const float* v3      = (const float*)d_in[23];
    const float* Wskip   = (const float*)d_in[24];
    const float* bskip   = (const float*)d_in[25];
    const float* Wc1     = (const float*)d_in[26];
    const float* bc1     = (const float*)d_in[27];
    const float* Wc2     = (const float*)d_in[28];
    const float* bc2     = (const float*)d_in[29];
    float* out = (float*)d_out;

    const int TPB = 256;
    k_count<<<(E_EDGES + TPB - 1) / TPB, TPB>>>(ei);
    k_scan1<<<NB_SCAN, SCAN_B>>>();
    k_scan23<<<NB_SCAN, 256>>>();
    k_scatter<<<(E_EDGES + TPB - 1) / TPB, TPB>>>(ei);
    k_prep<<<34, 256>>>(Wg, att_src, att_dst);
    k_sage1_fused<<<(N_NODES + 7) / 8, TPB>>>(x, W1l, W1r, b1, g1, be1, m1, v1);
    k_gat_csr<<<(N_NODES + 7) / 8, TPB>>>();
    k_gat_post<<<(N_NODES + 127) / 128, 256>>>(bg, g2, be2, m2, v2);
    k_sage3_cls<<<(N_NODES + 7) / 8, TPB>>>(x, W3l, W3r, b3, g3, be3, m3, v3, Wskip, bskip,
                                            Wc1, bc1, Wc2, bc2, out);
}